// round 17
// baseline (speedup 1.0000x reference)
#include <cuda_runtime.h>

#define BB 64
#define CC 64
#define TT 4096

// ---- packed f32x2 helpers (Blackwell FFMA2 path, PTX-only) -----------------
__device__ __forceinline__ unsigned long long pk2(float lo, float hi) {
    unsigned long long r;
    asm("mov.b64 %0, {%1, %2};" : "=l"(r) : "f"(lo), "f"(hi));
    return r;
}
__device__ __forceinline__ void upk2(float& lo, float& hi, unsigned long long v) {
    asm("mov.b64 {%0, %1}, %2;" : "=f"(lo), "=f"(hi) : "l"(v));
}
__device__ __forceinline__ unsigned long long fma2(unsigned long long a,
                                                   unsigned long long b,
                                                   unsigned long long c) {
    unsigned long long d;
    asm("fma.rn.f32x2 %0, %1, %2, %3;" : "=l"(d) : "l"(a), "l"(b), "l"(c));
    return d;
}
__device__ __forceinline__ unsigned long long add2(unsigned long long a,
                                                   unsigned long long b) {
    unsigned long long d;
    asm("add.rn.f32x2 %0, %1, %2;" : "=l"(d) : "l"(a), "l"(b));
    return d;
}
__device__ __forceinline__ unsigned long long mul2(unsigned long long a,
                                                   unsigned long long b) {
    unsigned long long d;
    asm("mul.rn.f32x2 %0, %1, %2;" : "=l"(d) : "l"(a), "l"(b));
    return d;
}

// HW tanh (MUFU.TANH): measured output rel_err ~1.6e-5 on this problem.
__device__ __forceinline__ float tanh_hw(float x) {
    float r;
    asm("tanh.approx.f32 %0, %1;" : "=f"(r) : "f"(x));
    return r;
}

// ---------------------------------------------------------------------------
// FUSED kernel: recurrence + readout in one pass. One CTA per batch row,
// 64 threads (2 warps), thread = channel c.
//
// Per step t (rec-MAC structure = R9's proven single-barrier pipelined form,
// 4 accumulators; R12/R16 experiments that deviated from it regressed):
//   - broadcast th_{t-1} AND x_{t-1} via shared (2 coalesced STS.32)
//   - one 2-warp __syncthreads
//   - rec-MAC  (critical): x_t  = dt*W_rec@th_{t-1} + (1-dt)x_{t-1} + dt*u_t
//   - y-MAC    (shadow)  : y_{t-1} = W_ff@x_{t-1} + b   -- independent of the
//     recurrence chain, fills the ~130 idle issue cyc/step the latency-bound
//     step leaves on each SMSP. Eliminates the separate ff kernel (63 us)
//     and its 32 MB xmem re-read.
// y is produced one step late; an epilogue handles y_{T-1}.
// ---------------------------------------------------------------------------
__device__ __forceinline__ void rec_step(
    float& x, float& th, float& ylag, float ut, int buf, int c,
    float dt, float omd, float bias,
    const unsigned long long* __restrict__ wr,   // dt*W_rec row, 32 pairs
    const unsigned long long* __restrict__ wf,   // W_ff row, 32 pairs
    float (*th_sh)[CC], float (*x_sh)[CC])
{
    float base = fmaf(dt, ut, omd * x);   // off-critical-path
    th_sh[buf][c] = th;                   // coalesced STS.32
    x_sh[buf][c]  = x;                    // coalesced STS.32
    __syncthreads();                      // 2-warp barrier (lockstep -> cheap)

    const ulonglong2* thv = (const ulonglong2*)(th_sh[buf]);
    const ulonglong2* xv  = (const ulonglong2*)(x_sh[buf]);

    unsigned long long a0 = pk2(base, 0.0f);          // rec acc (critical)
    unsigned long long a1 = 0ull, a2 = 0ull, a3 = 0ull;
    unsigned long long b0 = pk2(bias, 0.0f);          // y acc (shadow)
    unsigned long long b1 = 0ull, b2 = 0ull, b3 = 0ull;

#pragma unroll
    for (int j = 0; j < 8; j++) {         // 16+16 LDS.128 bcast, 32+32 FFMA2
        ulonglong2 v0 = thv[2 * j];
        ulonglong2 v1 = thv[2 * j + 1];
        a0 = fma2(wr[4 * j + 0], v0.x, a0);
        a1 = fma2(wr[4 * j + 1], v0.y, a1);
        a2 = fma2(wr[4 * j + 2], v1.x, a2);
        a3 = fma2(wr[4 * j + 3], v1.y, a3);
        ulonglong2 u0 = xv[2 * j];
        ulonglong2 u1 = xv[2 * j + 1];
        b0 = fma2(wf[4 * j + 0], u0.x, b0);
        b1 = fma2(wf[4 * j + 1], u0.y, b1);
        b2 = fma2(wf[4 * j + 2], u1.x, b2);
        b3 = fma2(wf[4 * j + 3], u1.y, b3);
    }

    // critical path: rec reduce -> x -> tanh
    unsigned long long sp = add2(add2(a0, a1), add2(a2, a3));
    float lo, hi; upk2(lo, hi, sp);
    x  = lo + hi;                         // base folded into a0
    th = tanh_hw(x);

    // shadow: y_{t-1} reduce
    unsigned long long sq = add2(add2(b0, b1), add2(b2, b3));
    float lo2, hi2; upk2(lo2, hi2, sq);
    ylag = lo2 + hi2;                     // bias folded into b0
}

__global__ __launch_bounds__(64, 1)
void fused_kernel(const float* __restrict__ u, const float* __restrict__ Wrec,
                  const float* __restrict__ Wff, const float* __restrict__ bff,
                  const float* __restrict__ dtp,
                  float* __restrict__ yout, float* __restrict__ xmem) {
    const int b = blockIdx.x;
    const int c = threadIdx.x;          // 0..63, one channel per thread

    __shared__ __align__(16) float th_sh[2][CC];
    __shared__ __align__(16) float x_sh[2][CC];

    const float dt  = *dtp;
    const float omd = 1.0f - dt;
    const float bias = bff[c];
    const unsigned long long dt2 = pk2(dt, dt);

    // W_rec row pre-scaled by dt; W_ff row unscaled. 32 packed pairs each.
    unsigned long long wr[32], wf[32];
    const unsigned long long* wrp = (const unsigned long long*)(Wrec + c * CC);
    const unsigned long long* wfp = (const unsigned long long*)(Wff  + c * CC);
#pragma unroll
    for (int j = 0; j < 32; j++) wr[j] = mul2(wrp[j], dt2);
#pragma unroll
    for (int j = 0; j < 32; j++) wf[j] = wfp[j];

    const float4* ub4 = (const float4*)(u    + (b * CC + c) * TT);
    float4*       xb4 = (float4*)      (xmem + (b * CC + c) * TT);
    float4*       yb4 = (float4*)      (yout + (b * CC + c) * TT);

    float x = 0.0f, th = 0.0f;          // x0 = 0, tanh(0) = 0
    float4 ucur  = ub4[0];
    float4 unext = ub4[1];
    float4 yq;                           // rolling quad of y values
    float yl;

    for (int t0 = 0; t0 < TT; t0 += 4) {
        float4 xout;
        // step t0: also yields y_{t0-1}, completing the previous y-quad
        rec_step(x, th, yl, ucur.x, 0, c, dt, omd, bias, wr, wf, th_sh, x_sh);
        xout.x = x;
        yq.w = yl;
        if (t0 > 0) yb4[(t0 >> 2) - 1] = yq;       // y[t0-4 .. t0-1]
        // steps t0+1..t0+3: yield y_{t0}, y_{t0+1}, y_{t0+2}
        rec_step(x, th, yl, ucur.y, 1, c, dt, omd, bias, wr, wf, th_sh, x_sh);
        xout.y = x; yq.x = yl;
        rec_step(x, th, yl, ucur.z, 0, c, dt, omd, bias, wr, wf, th_sh, x_sh);
        xout.z = x; yq.y = yl;
        rec_step(x, th, yl, ucur.w, 1, c, dt, omd, bias, wr, wf, th_sh, x_sh);
        xout.w = x; yq.z = yl;

        xb4[t0 >> 2] = xout;            // membrane trace x[t0 .. t0+3]
        ucur = unext;
        if (t0 + 8 < TT) unext = ub4[(t0 >> 2) + 2];
    }

    // epilogue: y_{T-1} = Wff @ x_{T-1} + b  (broadcast final x, buf 0)
    x_sh[0][c] = x;
    __syncthreads();
    {
        const ulonglong2* xv = (const ulonglong2*)(x_sh[0]);
        unsigned long long b0 = pk2(bias, 0.0f);
        unsigned long long b1 = 0ull, b2 = 0ull, b3 = 0ull;
#pragma unroll
        for (int j = 0; j < 8; j++) {
            ulonglong2 u0 = xv[2 * j];
            ulonglong2 u1 = xv[2 * j + 1];
            b0 = fma2(wf[4 * j + 0], u0.x, b0);
            b1 = fma2(wf[4 * j + 1], u0.y, b1);
            b2 = fma2(wf[4 * j + 2], u1.x, b2);
            b3 = fma2(wf[4 * j + 3], u1.y, b3);
        }
        unsigned long long sq = add2(add2(b0, b1), add2(b2, b3));
        float lo2, hi2; upk2(lo2, hi2, sq);
        yq.w = lo2 + hi2;
    }
    yb4[TT / 4 - 1] = yq;               // y[T-4 .. T-1]
}

// ---------------------------------------------------------------------------
extern "C" void kernel_launch(void* const* d_in, const int* in_sizes, int n_in,
                              void* d_out, int out_size) {
    const float* u    = (const float*)d_in[0];   // [B,C,T]
    const float* Wrec = (const float*)d_in[1];   // [C,C]
    const float* Wff  = (const float*)d_in[2];   // [C,C]
    const float* bff  = (const float*)d_in[3];   // [C]
    const float* dtp  = (const float*)d_in[4];   // scalar

    float* out  = (float*)d_out;
    float* yout = out;                            // outputs [B,C,T]
    float* xmem = out + (size_t)BB * CC * TT;     // membrane_potentials [B,C,T]

    fused_kernel<<<BB, 64>>>(u, Wrec, Wff, bff, dtp, yout, xmem);
}